// round 1
// baseline (speedup 1.0000x reference)
#include <cuda_runtime.h>
#include <cstdint>

#define Bb 2
#define Cch 64
#define Dd 3
#define Nn 4096
#define Kk 16
#define Hh 256

// ---------------- device scratch (static, no runtime alloc) ----------------
__device__ float d_mean[Bb*Cch*Nn];       // (B,C,N)
__device__ float d_ptsT[Bb*Nn*Cch];       // (B,N,C)
__device__ float d_sq[Bb*Nn];             // (B,N)
__device__ int   d_idx[Bb*Kk*Nn];         // (B,K,N)
__device__ float d_AT[Cch*Hh];            // (c-major) W1[:, :C] - W1[:, C:]
__device__ float d_BT[Cch*Hh];            // (c-major) W1[:, C:]
__device__ float d_U[Bb*Dd*Nn*Hh];        // per (b,d,n): 256 floats (incl b1)
__device__ float d_V[Bb*Kk*Nn*Hh];        // per (b,k,n): 256 floats

// ---------------- weight prep ----------------
__global__ void prep_w(const float* __restrict__ W1) {
    int e = blockIdx.x * 256 + threadIdx.x;          // 16384 total
    if (e < Cch*Hh) {
        int c = e / Hh, o = e % Hh;
        float wc = W1[o*128 + c];
        float wn = W1[o*128 + 64 + c];
        d_AT[c*Hh + o] = wc - wn;
        d_BT[c*Hh + o] = wn;
    }
}

// ---------------- mean over D ----------------
__global__ void mean_k(const float* __restrict__ x) {
    int e = blockIdx.x * 256 + threadIdx.x;          // 524288
    int b = e >> 18;
    int cn = e & 262143;
    int c = cn >> 12, n = cn & 4095;
    int base = ((b*Cch + c)*Dd)*Nn + n;
    d_mean[e] = (x[base] + x[base + Nn] + x[base + 2*Nn]) * (1.0f/3.0f);
}

__global__ void transpose_k() {
    int e = blockIdx.x * 256 + threadIdx.x;          // 524288
    int b = e >> 18;
    int cn = e & 262143;
    int c = cn >> 12, n = cn & 4095;
    d_ptsT[(b*Nn + n)*Cch + c] = d_mean[e];
}

__global__ void sq_k() {
    int i = blockIdx.x * 256 + threadIdx.x;          // 8192
    const float4* p = (const float4*)(d_ptsT + i*64);
    float s = 0.f;
#pragma unroll
    for (int t = 0; t < 16; t++) {
        float4 v = p[t];
        s += v.x*v.x + v.y*v.y + v.z*v.z + v.w*v.w;
    }
    d_sq[i] = s;
}

// ---------------- KNN: 16 nearest (self excluded) ----------------
__global__ void knn_k() {
    __shared__ float rs[128*64];
    __shared__ float rsq[128];
    int b = blockIdx.x >> 5;                          // 32 blocks per batch
    int n = ((blockIdx.x & 31) << 7) + threadIdx.x;   // query index

    float q[64];
    const float4* qp = (const float4*)(d_ptsT + (b*Nn + n)*64);
#pragma unroll
    for (int t = 0; t < 16; t++) {
        float4 v = qp[t];
        q[4*t] = v.x; q[4*t+1] = v.y; q[4*t+2] = v.z; q[4*t+3] = v.w;
    }
    float sqn = d_sq[b*Nn + n];

    float dist[16]; int ind[16];
#pragma unroll
    for (int s = 0; s < 16; s++) { dist[s] = __int_as_float(0x7f800000); ind[s] = 0; }

    for (int jt = 0; jt < 32; jt++) {
        __syncthreads();
        const float4* src = (const float4*)(d_ptsT + (b*Nn + jt*128)*64);
        for (int e = threadIdx.x; e < 2048; e += 128)
            ((float4*)rs)[e] = src[e];
        rsq[threadIdx.x] = d_sq[b*Nn + jt*128 + threadIdx.x];
        __syncthreads();

#pragma unroll 2
        for (int r = 0; r < 128; r++) {
            int j = jt*128 + r;
            float a0 = 0.f, a1 = 0.f, a2 = 0.f, a3 = 0.f;
            const float4* rv = (const float4*)(rs + r*64);
#pragma unroll
            for (int t = 0; t < 16; t++) {
                float4 v = rv[t];
                a0 = fmaf(q[4*t],   v.x, a0);
                a1 = fmaf(q[4*t+1], v.y, a1);
                a2 = fmaf(q[4*t+2], v.z, a2);
                a3 = fmaf(q[4*t+3], v.w, a3);
            }
            float d2 = sqn + rsq[r] - 2.0f*((a0+a1)+(a2+a3));
            if (j == n) continue;
            if (d2 < dist[15]) {
                float dd = d2; int jj = j;
#pragma unroll
                for (int s = 0; s < 16; s++) {
                    if (dd < dist[s]) {
                        float td = dist[s]; int ti = ind[s];
                        dist[s] = dd; ind[s] = jj;
                        dd = td; jj = ti;
                    }
                }
            }
        }
    }
#pragma unroll
    for (int s = 0; s < 16; s++)
        d_idx[(b*Kk + s)*Nn + n] = ind[s];
}

// ---------------- U = A @ central + b1   (256 x 64 GEMM over 32 n's) ----------------
__global__ __launch_bounds__(256) void u_kern(const float* __restrict__ x,
                                              const float* __restrict__ b1) {
    extern __shared__ float sm[];
    float* Ws = sm;                 // 16384 floats, [c][o]
    float* xs = sm + 16384;         // 64 x 36 (pad)
    int bx = blockIdx.x;            // 768 = 2*3*128
    int ng = bx & 127;
    int d  = (bx >> 7) % 3;
    int b  = bx / 384;
    int n0 = ng * 32;

    for (int e = threadIdx.x; e < 4096; e += 256)
        ((float4*)Ws)[e] = ((const float4*)d_AT)[e];
    for (int e = threadIdx.x; e < 2048; e += 256) {
        int c = e >> 5, p = e & 31;
        xs[c*36 + p] = x[((b*Cch + c)*Dd + d)*Nn + n0 + p];
    }
    __syncthreads();

    int o = threadIdx.x;
    float acc[32];
#pragma unroll
    for (int p = 0; p < 32; p++) acc[p] = 0.f;
#pragma unroll 4
    for (int c = 0; c < 64; c++) {
        float w = Ws[c*256 + o];
        const float4* xv = (const float4*)(xs + c*36);
#pragma unroll
        for (int p4 = 0; p4 < 8; p4++) {
            float4 v = xv[p4];
            acc[4*p4+0] = fmaf(w, v.x, acc[4*p4+0]);
            acc[4*p4+1] = fmaf(w, v.y, acc[4*p4+1]);
            acc[4*p4+2] = fmaf(w, v.z, acc[4*p4+2]);
            acc[4*p4+3] = fmaf(w, v.w, acc[4*p4+3]);
        }
    }
    float bb = b1[o];
    float* dst = d_U + (((b*Dd + d)*Nn) + n0)*Hh + o;
#pragma unroll
    for (int p = 0; p < 32; p++) dst[p*Hh] = acc[p] + bb;
}

// ---------------- V = Bm @ nbr   (gathered) ----------------
__global__ __launch_bounds__(256) void v_kern() {
    extern __shared__ float sm[];
    float* Ws = sm;
    float* gs = sm + 16384;
    int bx = blockIdx.x;            // 4096 = 2*16*128
    int ng = bx & 127;
    int k  = (bx >> 7) & 15;
    int b  = bx >> 11;
    int n0 = ng * 32;

    for (int e = threadIdx.x; e < 4096; e += 256)
        ((float4*)Ws)[e] = ((const float4*)d_BT)[e];
    for (int e = threadIdx.x; e < 2048; e += 256) {
        int p = e >> 6, c = e & 63;
        int j = d_idx[(b*Kk + k)*Nn + n0 + p];
        gs[c*36 + p] = d_ptsT[(b*Nn + j)*Cch + c];
    }
    __syncthreads();

    int o = threadIdx.x;
    float acc[32];
#pragma unroll
    for (int p = 0; p < 32; p++) acc[p] = 0.f;
#pragma unroll 4
    for (int c = 0; c < 64; c++) {
        float w = Ws[c*256 + o];
        const float4* xv = (const float4*)(gs + c*36);
#pragma unroll
        for (int p4 = 0; p4 < 8; p4++) {
            float4 v = xv[p4];
            acc[4*p4+0] = fmaf(w, v.x, acc[4*p4+0]);
            acc[4*p4+1] = fmaf(w, v.y, acc[4*p4+1]);
            acc[4*p4+2] = fmaf(w, v.z, acc[4*p4+2]);
            acc[4*p4+3] = fmaf(w, v.w, acc[4*p4+3]);
        }
    }
    float* dst = d_V + (((b*Kk + k)*Nn) + n0)*Hh + o;
#pragma unroll
    for (int p = 0; p < 32; p++) dst[p*Hh] = acc[p];
}

// ---------------- fused layer2 + layer3 + max_k + residual ----------------
// block: (b, d, 4 n's, all 16 k) = 64 points of 256-dim hidden
__global__ __launch_bounds__(256) void mlp2_kern(const float* __restrict__ x,
                                                 const float* __restrict__ W2,
                                                 const float* __restrict__ b2,
                                                 const float* __restrict__ W3,
                                                 const float* __restrict__ b3,
                                                 float* __restrict__ out) {
    extern __shared__ float sm[];
    float* h1s = sm;            // 64*256 = 16384 (region sized 16640; reused as W3s 64*260)
    float* h2s = sm + 16640;    // 64*256
    float* w2s = sm + 33024;    // 256*36 (chunk of 32 i's, padded)

    int bx = blockIdx.x;        // 6144 = 2*3*1024
    int ng = bx & 1023;
    int d  = (bx >> 10) % 3;
    int b  = bx / 3072;
    int n0 = ng * 4;
    int tid = threadIdx.x;

    // stage1: h1[p][i] = relu(U[b,d,n] + V[b,k,n]),  p = nl*16 + k
    for (int e = tid; e < 4096; e += 256) {          // float4 granules
        int p = e >> 6, iv = e & 63;
        int nl = p >> 4, k = p & 15;
        float4 u = ((const float4*)d_U)[((((b*Dd + d)*Nn) + n0 + nl)*64) + iv];
        float4 v = ((const float4*)d_V)[((((b*Kk + k)*Nn) + n0 + nl)*64) + iv];
        float4 h;
        h.x = fmaxf(u.x + v.x, 0.f);
        h.y = fmaxf(u.y + v.y, 0.f);
        h.z = fmaxf(u.z + v.z, 0.f);
        h.w = fmaxf(u.w + v.w, 0.f);
        ((float4*)h1s)[p*64 + iv] = h;
    }

    // stage2: h2[o] = relu(W2[o,:] @ h1 + b2[o]) for 64 points, thread = o
    int o = tid;
    float acc[64];
#pragma unroll
    for (int p = 0; p < 64; p++) acc[p] = 0.f;

    for (int ic = 0; ic < 8; ic++) {
        __syncthreads();
        for (int e = tid; e < 2048; e += 256) {       // load W2 chunk [256 o][32 i]
            int oo = e >> 3, j4 = e & 7;
            ((float4*)w2s)[oo*9 + j4] = ((const float4*)W2)[oo*64 + ic*8 + j4];
        }
        __syncthreads();
#pragma unroll
        for (int i4 = 0; i4 < 8; i4++) {
            float4 w = ((const float4*)w2s)[o*9 + i4];
            const float4* hp = (const float4*)h1s + (ic*8 + i4);
#pragma unroll
            for (int p = 0; p < 64; p++) {
                float4 h = hp[p*64];
                acc[p] = fmaf(w.x, h.x, acc[p]);
                acc[p] = fmaf(w.y, h.y, acc[p]);
                acc[p] = fmaf(w.z, h.z, acc[p]);
                acc[p] = fmaf(w.w, h.w, acc[p]);
            }
        }
    }
    __syncthreads();
    float bo = b2[o];
#pragma unroll
    for (int p = 0; p < 64; p++)
        h2s[p*256 + o] = fmaxf(acc[p] + bo, 0.f);

    // load W3 [c][i] into h1s region, padded stride 260 floats (65 float4)
    for (int e = tid; e < 4096; e += 256) {
        int c = e >> 6, iv = e & 63;
        ((float4*)h1s)[c*65 + iv] = ((const float4*)W3)[e];
    }
    __syncthreads();

    // stage3: r[c] = W3[c,:] @ h2 ; thread = (c = tid%64, pg = tid/64) -> p in [pg*16, pg*16+16)
    int c  = tid & 63;
    int pg = tid >> 6;
    float a3[16];
#pragma unroll
    for (int pp = 0; pp < 16; pp++) a3[pp] = 0.f;
#pragma unroll 4
    for (int i4 = 0; i4 < 64; i4++) {
        float4 w = ((const float4*)h1s)[c*65 + i4];
        const float4* hp = (const float4*)h2s + i4;
#pragma unroll
        for (int pp = 0; pp < 16; pp++) {
            float4 h = hp[(pg*16 + pp)*64];
            a3[pp] = fmaf(w.x, h.x, a3[pp]);
            a3[pp] = fmaf(w.y, h.y, a3[pp]);
            a3[pp] = fmaf(w.z, h.z, a3[pp]);
            a3[pp] = fmaf(w.w, h.w, a3[pp]);
        }
    }

    // max over k (p = nl*16 + k, pg == nl so the 16 accs are exactly k=0..15)
    float m = a3[0];
#pragma unroll
    for (int pp = 1; pp < 16; pp++) m = fmaxf(m, a3[pp]);
    int n = n0 + pg;
    int oi = ((b*Cch + c)*Dd + d)*Nn + n;
    out[oi] = m + b3[c] + x[oi];
}

// ---------------- launch ----------------
extern "C" void kernel_launch(void* const* d_in, const int* in_sizes, int n_in,
                              void* d_out, int out_size) {
    const float* x  = (const float*)d_in[0];
    const float* W1 = (const float*)d_in[1];
    const float* b1 = (const float*)d_in[2];
    const float* W2 = (const float*)d_in[3];
    const float* b2 = (const float*)d_in[4];
    const float* W3 = (const float*)d_in[5];
    const float* b3 = (const float*)d_in[6];
    float* out = (float*)d_out;

    static bool attr_done = false;
    if (!attr_done) {
        cudaFuncSetAttribute(u_kern,    cudaFuncAttributeMaxDynamicSharedMemorySize, 74752);
        cudaFuncSetAttribute(v_kern,    cudaFuncAttributeMaxDynamicSharedMemorySize, 74752);
        cudaFuncSetAttribute(mlp2_kern, cudaFuncAttributeMaxDynamicSharedMemorySize, 168960);
        attr_done = true;
    }

    prep_w<<<64, 256>>>(W1);
    mean_k<<<2048, 256>>>(x);
    transpose_k<<<2048, 256>>>();
    sq_k<<<32, 256>>>();
    knn_k<<<64, 128>>>();
    u_kern<<<768, 256, 74752>>>(x, b1);
    v_kern<<<4096, 256, 74752>>>();
    mlp2_kern<<<6144, 256, 168960>>>(x, W2, b2, W3, b3, out);
}

// round 6
// speedup vs baseline: 1.6931x; 1.6931x over previous
#include <cuda_runtime.h>
#include <cstdint>

#define Bb 2
#define Cch 64
#define Dd 3
#define Nn 4096
#define Kk 16
#define Hh 256

// ---------------- device scratch ----------------
__device__ float d_mean[Bb*Cch*Nn];
__device__ float d_ptsT[Bb*Nn*Cch];
__device__ float d_sq[Bb*Nn];
__device__ int   d_idx[Bb*Kk*Nn];
__device__ float d_AT[Cch*Hh];
__device__ float d_BT[Cch*Hh];
__device__ float d_U[Bb*Dd*Nn*Hh];
__device__ float d_V[Bb*Kk*Nn*Hh];
__device__ float d_pdist[Bb*4*16*Nn];
__device__ int   d_pidx[Bb*4*16*Nn];

// ---------------- helpers ----------------
__device__ __forceinline__ uint32_t tf32r(float f) {
    uint32_t r; asm("cvt.rna.tf32.f32 %0, %1;" : "=r"(r) : "f"(f)); return r;
}

__device__ __forceinline__ void mma_tf32(float* c, const uint32_t* a, const uint32_t* b) {
    asm volatile("mma.sync.aligned.m16n8k8.row.col.f32.tf32.tf32.f32 "
        "{%0,%1,%2,%3}, {%4,%5,%6,%7}, {%8,%9}, {%0,%1,%2,%3};"
        : "+f"(c[0]), "+f"(c[1]), "+f"(c[2]), "+f"(c[3])
        : "r"(a[0]), "r"(a[1]), "r"(a[2]), "r"(a[3]), "r"(b[0]), "r"(b[1]));
}

// ---------------- weight prep ----------------
__global__ void prep_w(const float* __restrict__ W1) {
    int e = blockIdx.x * 256 + threadIdx.x;
    if (e < Cch*Hh) {
        int c = e / Hh, o = e % Hh;
        float wc = W1[o*128 + c];
        float wn = W1[o*128 + 64 + c];
        d_AT[c*Hh + o] = wc - wn;
        d_BT[c*Hh + o] = wn;
    }
}

__global__ void mean_k(const float* __restrict__ x) {
    int e = blockIdx.x * 256 + threadIdx.x;
    int b = e >> 18;
    int cn = e & 262143;
    int c = cn >> 12, n = cn & 4095;
    int base = ((b*Cch + c)*Dd)*Nn + n;
    d_mean[e] = (x[base] + x[base + Nn] + x[base + 2*Nn]) * (1.0f/3.0f);
}

__global__ void transpose_k() {
    int e = blockIdx.x * 256 + threadIdx.x;
    int b = e >> 18;
    int cn = e & 262143;
    int c = cn >> 12, n = cn & 4095;
    d_ptsT[(b*Nn + n)*Cch + c] = d_mean[e];
}

__global__ void sq_k() {
    int i = blockIdx.x * 256 + threadIdx.x;
    const float4* p = (const float4*)(d_ptsT + i*64);
    float s = 0.f;
#pragma unroll
    for (int t = 0; t < 16; t++) {
        float4 v = p[t];
        s += v.x*v.x + v.y*v.y + v.z*v.z + v.w*v.w;
    }
    d_sq[i] = s;
}

// ---------------- KNN part: each block scans 1/4 of the candidates ----------------
__global__ void knn_part() {
    __shared__ float rs[128*64];
    __shared__ float rsq[128];
    int bx = blockIdx.x;                 // 256 = 2b * 32qt * 4js
    int js = bx & 3;
    int qt = (bx >> 2) & 31;
    int b  = bx >> 7;
    int n  = qt*128 + threadIdx.x;

    float q[64];
    const float4* qp = (const float4*)(d_ptsT + (b*Nn + n)*64);
#pragma unroll
    for (int t = 0; t < 16; t++) {
        float4 v = qp[t];
        q[4*t] = v.x; q[4*t+1] = v.y; q[4*t+2] = v.z; q[4*t+3] = v.w;
    }
    float sqn = d_sq[b*Nn + n];

    float dist[16]; int ind[16];
#pragma unroll
    for (int s = 0; s < 16; s++) { dist[s] = __int_as_float(0x7f800000); ind[s] = 0; }

    for (int jt = js*8; jt < js*8 + 8; jt++) {
        __syncthreads();
        const float4* src = (const float4*)(d_ptsT + (b*Nn + jt*128)*64);
        for (int e = threadIdx.x; e < 2048; e += 128)
            ((float4*)rs)[e] = src[e];
        rsq[threadIdx.x] = d_sq[b*Nn + jt*128 + threadIdx.x];
        __syncthreads();

#pragma unroll 2
        for (int r = 0; r < 128; r++) {
            int j = jt*128 + r;
            float a0 = 0.f, a1 = 0.f, a2 = 0.f, a3 = 0.f;
            const float4* rv = (const float4*)(rs + r*64);
#pragma unroll
            for (int t = 0; t < 16; t++) {
                float4 v = rv[t];
                a0 = fmaf(q[4*t],   v.x, a0);
                a1 = fmaf(q[4*t+1], v.y, a1);
                a2 = fmaf(q[4*t+2], v.z, a2);
                a3 = fmaf(q[4*t+3], v.w, a3);
            }
            float d2 = sqn + rsq[r] - 2.0f*((a0+a1)+(a2+a3));
            if (j == n) continue;
            if (d2 < dist[15]) {
                float dd = d2; int jj = j;
#pragma unroll
                for (int s = 0; s < 16; s++) {
                    if (dd < dist[s]) {
                        float td = dist[s]; int ti = ind[s];
                        dist[s] = dd; ind[s] = jj;
                        dd = td; jj = ti;
                    }
                }
            }
        }
    }
#pragma unroll
    for (int s = 0; s < 16; s++) {
        int o = ((b*4 + js)*16 + s)*Nn + n;
        d_pdist[o] = dist[s];
        d_pidx[o]  = ind[s];
    }
}

// ---------------- KNN merge: 4 sorted 16-lists -> final 16 set ----------------
__global__ void knn_merge() {
    int e = blockIdx.x * 256 + threadIdx.x;     // 8192
    int b = e >> 12, n = e & 4095;

    float dist[16]; int ind[16];
#pragma unroll
    for (int s = 0; s < 16; s++) { dist[s] = __int_as_float(0x7f800000); ind[s] = 0; }

    for (int js = 0; js < 4; js++) {
#pragma unroll
        for (int s = 0; s < 16; s++) {
            int o = ((b*4 + js)*16 + s)*Nn + n;
            float dd = d_pdist[o];
            int jj = d_pidx[o];
            if (dd < dist[15]) {
#pragma unroll
                for (int t = 0; t < 16; t++) {
                    if (dd < dist[t]) {
                        float td = dist[t]; int ti = ind[t];
                        dist[t] = dd; ind[t] = jj;
                        dd = td; jj = ti;
                    }
                }
            }
        }
    }
#pragma unroll
    for (int s = 0; s < 16; s++)
        d_idx[(b*Kk + s)*Nn + n] = ind[s];
}

// ---------------- U kernel ----------------
__global__ __launch_bounds__(256) void u_kern(const float* __restrict__ x,
                                              const float* __restrict__ b1) {
    extern __shared__ float sm[];
    float* Ws = sm;
    float* xs = sm + 16384;
    int bx = blockIdx.x;
    int ng = bx & 127;
    int d  = (bx >> 7) % 3;
    int b  = bx / 384;
    int n0 = ng * 32;

    for (int e = threadIdx.x; e < 4096; e += 256)
        ((float4*)Ws)[e] = ((const float4*)d_AT)[e];
    for (int e = threadIdx.x; e < 2048; e += 256) {
        int c = e >> 5, p = e & 31;
        xs[c*36 + p] = x[((b*Cch + c)*Dd + d)*Nn + n0 + p];
    }
    __syncthreads();

    int o = threadIdx.x;
    float acc[32];
#pragma unroll
    for (int p = 0; p < 32; p++) acc[p] = 0.f;
#pragma unroll 4
    for (int c = 0; c < 64; c++) {
        float w = Ws[c*256 + o];
        const float4* xv = (const float4*)(xs + c*36);
#pragma unroll
        for (int p4 = 0; p4 < 8; p4++) {
            float4 v = xv[p4];
            acc[4*p4+0] = fmaf(w, v.x, acc[4*p4+0]);
            acc[4*p4+1] = fmaf(w, v.y, acc[4*p4+1]);
            acc[4*p4+2] = fmaf(w, v.z, acc[4*p4+2]);
            acc[4*p4+3] = fmaf(w, v.w, acc[4*p4+3]);
        }
    }
    float bb = b1[o];
    float* dst = d_U + (((b*Dd + d)*Nn) + n0)*Hh + o;
#pragma unroll
    for (int p = 0; p < 32; p++) dst[p*Hh] = acc[p] + bb;
}

// ---------------- V kernel ----------------
__global__ __launch_bounds__(256) void v_kern() {
    extern __shared__ float sm[];
    float* Ws = sm;
    float* gs = sm + 16384;
    int bx = blockIdx.x;
    int ng = bx & 127;
    int k  = (bx >> 7) & 15;
    int b  = bx >> 11;
    int n0 = ng * 32;

    for (int e = threadIdx.x; e < 4096; e += 256)
        ((float4*)Ws)[e] = ((const float4*)d_BT)[e];
    for (int e = threadIdx.x; e < 2048; e += 256) {
        int p = e >> 6, c = e & 63;
        int j = d_idx[(b*Kk + k)*Nn + n0 + p];
        gs[c*36 + p] = d_ptsT[(b*Nn + j)*Cch + c];
    }
    __syncthreads();

    int o = threadIdx.x;
    float acc[32];
#pragma unroll
    for (int p = 0; p < 32; p++) acc[p] = 0.f;
#pragma unroll 4
    for (int c = 0; c < 64; c++) {
        float w = Ws[c*256 + o];
        const float4* xv = (const float4*)(gs + c*36);
#pragma unroll
        for (int p4 = 0; p4 < 8; p4++) {
            float4 v = xv[p4];
            acc[4*p4+0] = fmaf(w, v.x, acc[4*p4+0]);
            acc[4*p4+1] = fmaf(w, v.y, acc[4*p4+1]);
            acc[4*p4+2] = fmaf(w, v.z, acc[4*p4+2]);
            acc[4*p4+3] = fmaf(w, v.w, acc[4*p4+3]);
        }
    }
    float* dst = d_V + (((b*Kk + k)*Nn) + n0)*Hh + o;
#pragma unroll
    for (int p = 0; p < 32; p++) dst[p*Hh] = acc[p];
}

// ---------------- mma.sync tf32 fused layer2+layer3+max+residual ----------------
// SMEM floats:
//   h1/h2 : [128 p][stride 260]            offset 0      (33280)
//   Bs    : W2 chunks 2x[256 o][stride 36] offset 33280  (18432 region)
//           later W3 [64 c][stride 260], later r [128 p][stride 66]
//   b2s   : offset 51712 (256)
//   b3s   : offset 51968 (64)
#define SM_BS   33280
#define SM_B2S  51712
#define SM_B3S  51968
#define SM_TOTF 52032
#define SM_TOTB (SM_TOTF*4)

__global__ __launch_bounds__(256, 1) void mlp2_mma(const float* __restrict__ x,
                                                   const float* __restrict__ W2,
                                                   const float* __restrict__ b2,
                                                   const float* __restrict__ W3,
                                                   const float* __restrict__ b3,
                                                   float* __restrict__ out) {
    extern __shared__ float smf[];
    uint32_t* h1u = (uint32_t*)smf;
    int tid = threadIdx.x;
    int wid = tid >> 5, lid = tid & 31;
    int row = lid >> 2, tg = lid & 3;     // fragment row / thread-in-group

    int bx = blockIdx.x;                  // 3072 = 2*3*512
    int ng = bx & 511;
    int d  = (bx >> 9) % 3;
    int b  = bx / 1536;
    int n0 = ng * 8;

    if (tid < 256) smf[SM_B2S + tid] = b2[tid];
    if (tid < 64)  smf[SM_B3S + tid] = b3[tid];

    // ---- phase 1: h1 = tf32(relu(U+V)) -> smem [p][i], stride 260 ----
    {
        const float4* Vp = (const float4*)d_V;
        const float4* Up = (const float4*)d_U;
        for (int e = tid; e < 8192; e += 256) {
            int p = e >> 6, iv = e & 63;
            int nl = p >> 4, kk = p & 15;
            float4 v = Vp[((b*16 + kk)*4096 + n0 + nl)*64 + iv];
            float4 u = Up[((b*3  + d )*4096 + n0 + nl)*64 + iv];
            uint4 h;
            h.x = tf32r(fmaxf(u.x + v.x, 0.f));
            h.y = tf32r(fmaxf(u.y + v.y, 0.f));
            h.z = tf32r(fmaxf(u.z + v.z, 0.f));
            h.w = tf32r(fmaxf(u.w + v.w, 0.f));
            *(uint4*)(h1u + p*260 + iv*4) = h;
        }
    }

    // ---- GEMM1: D[128p][256o] = h1 . W2^T ----
    int wm = wid & 1, wn = wid >> 1;
    int pb = wm * 64, ob = wn * 64;

    float acc[4][8][4];
#pragma unroll
    for (int mi = 0; mi < 4; mi++)
#pragma unroll
        for (int ni = 0; ni < 8; ni++)
#pragma unroll
            for (int r = 0; r < 4; r++) acc[mi][ni][r] = 0.f;

    const float4* W2v = (const float4*)W2;
    float4 g[8];
#pragma unroll
    for (int j = 0; j < 8; j++) g[j] = W2v[tid*64 + j];      // chunk 0 prefetch

    for (int ch = 0; ch < 8; ch++) {
        int buf = ch & 1;
        uint32_t* Bs = h1u + SM_BS + buf*9216;
        // store staged chunk: Bs[o=tid][i_local], stride 36
#pragma unroll
        for (int j = 0; j < 8; j++) {
            uint4 q;
            q.x = tf32r(g[j].x); q.y = tf32r(g[j].y);
            q.z = tf32r(g[j].z); q.w = tf32r(g[j].w);
            *(uint4*)(Bs + tid*36 + j*4) = q;
        }
        __syncthreads();
        if (ch < 7) {
#pragma unroll
            for (int j = 0; j < 8; j++) g[j] = W2v[tid*64 + (ch+1)*8 + j];
        }
        const uint32_t* Bsr = h1u + SM_BS + buf*9216;
#pragma unroll
        for (int k8 = 0; k8 < 4; k8++) {
            int kb = ch*32 + k8*8;
            uint32_t a[4][4];
#pragma unroll
            for (int mi = 0; mi < 4; mi++) {
                int p0 = pb + mi*16 + row;
                a[mi][0] = h1u[p0*260 + kb + tg];
                a[mi][1] = h1u[(p0+8)*260 + kb + tg];
                a[mi][2] = h1u[p0*260 + kb + tg + 4];
                a[mi][3] = h1u[(p0+8)*260 + kb + tg + 4];
            }
            uint32_t bq[8][2];
#pragma unroll
            for (int ni = 0; ni < 8; ni++) {
                int o = ob + ni*8 + row;
                bq[ni][0] = Bsr[o*36 + k8*8 + tg];
                bq[ni][1] = Bsr[o*36 + k8*8 + tg + 4];
            }
#pragma unroll
            for (int mi = 0; mi < 4; mi++)
#pragma unroll
                for (int ni = 0; ni < 8; ni++)
                    mma_tf32(acc[mi][ni], a[mi], bq[ni]);
        }
        __syncthreads();
    }

    // ---- epilogue1: h2 = tf32(relu(D + b2)) -> back into h1 region ----
    __syncthreads();
#pragma unroll
    for (int mi = 0; mi < 4; mi++) {
#pragma unroll
        for (int ni = 0; ni < 8; ni++) {
            int p = pb + mi*16 + row;
            int o = ob + ni*8 + 2*tg;
            float bo0 = smf[SM_B2S + o], bo1 = smf[SM_B2S + o + 1];
            uint2 v0, v1;
            v0.x = tf32r(fmaxf(acc[mi][ni][0] + bo0, 0.f));
            v0.y = tf32r(fmaxf(acc[mi][ni][1] + bo1, 0.f));
            v1.x = tf32r(fmaxf(acc[mi][ni][2] + bo0, 0.f));
            v1.y = tf32r(fmaxf(acc[mi][ni][3] + bo1, 0.f));
            *(uint2*)(h1u + p*260 + o)     = v0;
            *(uint2*)(h1u + (p+8)*260 + o) = v1;
        }
    }
    __syncthreads();

    // ---- stage W3 [64c][256i] -> Bs region, stride 260 ----
    {
        uint32_t* W3s = h1u + SM_BS;
        const float4* W3v = (const float4*)W3;
        for (int e = tid; e < 4096; e += 256) {
            int c = e >> 6, iv = e & 63;
            float4 gv = W3v[e];
            uint4 q;
            q.x = tf32r(gv.x); q.y = tf32r(gv.y);
            q.z = tf32r(gv.z); q.w = tf32r(gv.w);
            *(uint4*)(W3s + c*260 + iv*4) = q;
        }
    }
    __syncthreads();

    // ---- GEMM2: D2[128p][64c] = h2 . W3^T ----
    int pb2 = (wid & 1) * 64;
    int cb  = (wid >> 1) * 16;
    float ac2[4][2][4];
#pragma unroll
    for (int mi = 0; mi < 4; mi++)
#pragma unroll
        for (int ni = 0; ni < 2; ni++)
#pragma unroll
            for (int r = 0; r < 4; r++) ac2[mi][ni][r] = 0.f;

    const uint32_t* W3s = h1u + SM_BS;
#pragma unroll 4
    for (int ks = 0; ks < 32; ks++) {
        int kb = ks*8;
        uint32_t a[4][4];
#pragma unroll
        for (int mi = 0; mi < 4; mi++) {
            int p0 = pb2 + mi*16 + row;
            a[mi][0] = h1u[p0*260 + kb + tg];
            a[mi][1] = h1u[(p0+8)*260 + kb + tg];
            a[mi][2] = h1u[p0*260 + kb + tg + 4];
            a[mi][3] = h1u[(p0+8)*260 + kb + tg + 4];
        }
        uint32_t bq[2][2];
#pragma unroll
        for (int ni = 0; ni < 2; ni++) {
            int c = cb + ni*8 + row;
            bq[ni][0] = W3s[c*260 + kb + tg];
            bq[ni][1] = W3s[c*260 + kb + tg + 4];
        }
#pragma unroll
        for (int mi = 0; mi < 4; mi++)
#pragma unroll
            for (int ni = 0; ni < 2; ni++)
                mma_tf32(ac2[mi][ni], a[mi], bq[ni]);
    }
    __syncthreads();

    // ---- stage r = D2 -> Bs region, [p][c] stride 66 ----
    {
        float* rsm = smf + SM_BS;
#pragma unroll
        for (int mi = 0; mi < 4; mi++) {
#pragma unroll
            for (int ni = 0; ni < 2; ni++) {
                int p = pb2 + mi*16 + row;
                int c = cb + ni*8 + 2*tg;
                *(float2*)(rsm + p*66 + c)     = make_float2(ac2[mi][ni][0], ac2[mi][ni][1]);
                *(float2*)(rsm + (p+8)*66 + c) = make_float2(ac2[mi][ni][2], ac2[mi][ni][3]);
            }
        }
    }
    __syncthreads();

    // ---- max over k + bias + residual ----
    {
        const float* rsm = smf + SM_BS;
        for (int e = tid; e < 512; e += 256) {
            int nl = e >> 6, c = e & 63;
            float m = -3.4e38f;
#pragma unroll
            for (int kk = 0; kk < 16; kk++)
                m = fmaxf(m, rsm[(nl*16 + kk)*66 + c]);
            int oi = ((b*64 + c)*3 + d)*4096 + n0 + nl;
            out[oi] = m + smf[SM_B3S + c] + x[oi];
        }
    }
}

// ---------------- launch ----------------
extern "C" void kernel_launch(void* const* d_in, const int* in_sizes, int n_in,
                              void* d_out, int out_size) {
    const float* x  = (const float*)d_in[0];
    const float* W1 = (const float*)d_in[1];
    const float* b1 = (const float*)d_in[2];
    const float* W2 = (const float*)d_in[3];
    const float* b2 = (const float*)d_in[4];
    const float* W3 = (const float*)d_in[5];
    const float* b3 = (const float*)d_in[6];
    float* out = (float*)d_out;

    static bool attr_done = false;
    if (!attr_done) {
        cudaFuncSetAttribute(u_kern,   cudaFuncAttributeMaxDynamicSharedMemorySize, 74752);
        cudaFuncSetAttribute(v_kern,   cudaFuncAttributeMaxDynamicSharedMemorySize, 74752);
        cudaFuncSetAttribute(mlp2_mma, cudaFuncAttributeMaxDynamicSharedMemorySize, SM_TOTB);
        attr_done = true;
    }

    prep_w<<<64, 256>>>(W1);
    mean_k<<<2048, 256>>>(x);
    transpose_k<<<2048, 256>>>();
    sq_k<<<32, 256>>>();
    knn_part<<<256, 128>>>();
    knn_merge<<<32, 256>>>();
    u_kern<<<768, 256, 74752>>>(x, b1);
    v_kern<<<4096, 256, 74752>>>();
    mlp2_mma<<<3072, 256, SM_TOTB>>>(x, W2, b2, W3, b3, out);
}

// round 9
// speedup vs baseline: 4.1027x; 2.4232x over previous
#include <cuda_runtime.h>
#include <cuda_fp16.h>
#include <cstdint>

#define Bb 2
#define Cch 64
#define Dd 3
#define Nn 4096
#define Kk 16
#define Hh 256

// ---------------- device scratch ----------------
__device__ float  d_mean[Bb*Cch*Nn];
__device__ float  d_ptsT[Bb*Nn*Cch];
__device__ __half d_ptsTh[Bb*Nn*Cch];
__device__ float  d_sq[Bb*Nn];
__device__ int    d_idx[Bb*Kk*Nn];
__device__ float  d_AT[Cch*Hh];
__device__ __half d_BTh[Hh*Cch];          // [o][c]
__device__ __half d_W2h[Hh*Hh];           // [o][i]
__device__ __half d_W3h[Cch*Hh];          // [c][i]
__device__ __half d_U[Bb*Dd*Nn*Hh];
__device__ __half d_V[Bb*Kk*Nn*Hh];
__device__ float  d_pdist[Bb*4*16*Nn];
__device__ int    d_pidx[Bb*4*16*Nn];

// ---------------- helpers ----------------
__device__ __forceinline__ void mma_fp16(float* c, const uint32_t* a, const uint32_t* b) {
    asm volatile("mma.sync.aligned.m16n8k16.row.col.f32.f16.f16.f32 "
        "{%0,%1,%2,%3}, {%4,%5,%6,%7}, {%8,%9}, {%0,%1,%2,%3};"
        : "+f"(c[0]), "+f"(c[1]), "+f"(c[2]), "+f"(c[3])
        : "r"(a[0]), "r"(a[1]), "r"(a[2]), "r"(a[3]), "r"(b[0]), "r"(b[1]));
}
__device__ __forceinline__ uint32_t ldh2(const __half* p) {
    return *(const uint32_t*)p;
}

// ---------------- weight prep ----------------
__global__ void prep_w(const float* __restrict__ W1) {
    int e = blockIdx.x * 256 + threadIdx.x;          // 16384
    if (e < Cch*Hh) {
        int c = e / Hh, o = e % Hh;
        float wc = W1[o*128 + c];
        float wn = W1[o*128 + 64 + c];
        d_AT[c*Hh + o] = wc - wn;
        d_BTh[o*Cch + c] = __float2half_rn(wn);
    }
}

__global__ void prep_w23(const float* __restrict__ W2, const float* __restrict__ W3) {
    int e = blockIdx.x * 256 + threadIdx.x;          // 81920
    if (e < 65536)      d_W2h[e] = __float2half_rn(W2[e]);
    else if (e < 81920) d_W3h[e - 65536] = __float2half_rn(W3[e - 65536]);
}

__global__ void mean_k(const float* __restrict__ x) {
    int e = blockIdx.x * 256 + threadIdx.x;
    int b = e >> 18;
    int cn = e & 262143;
    int c = cn >> 12, n = cn & 4095;
    int base = ((b*Cch + c)*Dd)*Nn + n;
    d_mean[e] = (x[base] + x[base + Nn] + x[base + 2*Nn]) * (1.0f/3.0f);
}

__global__ void transpose_k() {
    int e = blockIdx.x * 256 + threadIdx.x;
    int b = e >> 18;
    int cn = e & 262143;
    int c = cn >> 12, n = cn & 4095;
    float v = d_mean[e];
    d_ptsT[(b*Nn + n)*Cch + c] = v;
    d_ptsTh[(b*Nn + n)*Cch + c] = __float2half_rn(v);
}

__global__ void sq_k() {
    int i = blockIdx.x * 256 + threadIdx.x;
    const float4* p = (const float4*)(d_ptsT + i*64);
    float s = 0.f;
#pragma unroll
    for (int t = 0; t < 16; t++) {
        float4 v = p[t];
        s += v.x*v.x + v.y*v.y + v.z*v.z + v.w*v.w;
    }
    d_sq[i] = s;
}

// ---------------- KNN part ----------------
__global__ void knn_part() {
    __shared__ float rs[128*64];
    __shared__ float rsq[128];
    int bx = blockIdx.x;                 // 256 = 2b * 32qt * 4js
    int js = bx & 3;
    int qt = (bx >> 2) & 31;
    int b  = bx >> 7;
    int n  = qt*128 + threadIdx.x;

    float q[64];
    const float4* qp = (const float4*)(d_ptsT + (b*Nn + n)*64);
#pragma unroll
    for (int t = 0; t < 16; t++) {
        float4 v = qp[t];
        q[4*t] = v.x; q[4*t+1] = v.y; q[4*t+2] = v.z; q[4*t+3] = v.w;
    }
    float sqn = d_sq[b*Nn + n];

    float dist[16]; int ind[16];
#pragma unroll
    for (int s = 0; s < 16; s++) { dist[s] = __int_as_float(0x7f800000); ind[s] = 0; }

    for (int jt = js*8; jt < js*8 + 8; jt++) {
        __syncthreads();
        const float4* src = (const float4*)(d_ptsT + (b*Nn + jt*128)*64);
        for (int e = threadIdx.x; e < 2048; e += 128)
            ((float4*)rs)[e] = src[e];
        rsq[threadIdx.x] = d_sq[b*Nn + jt*128 + threadIdx.x];
        __syncthreads();

#pragma unroll 2
        for (int r = 0; r < 128; r++) {
            int j = jt*128 + r;
            float a0 = 0.f, a1 = 0.f, a2 = 0.f, a3 = 0.f;
            const float4* rv = (const float4*)(rs + r*64);
#pragma unroll
            for (int t = 0; t < 16; t++) {
                float4 v = rv[t];
                a0 = fmaf(q[4*t],   v.x, a0);
                a1 = fmaf(q[4*t+1], v.y, a1);
                a2 = fmaf(q[4*t+2], v.z, a2);
                a3 = fmaf(q[4*t+3], v.w, a3);
            }
            float d2 = sqn + rsq[r] - 2.0f*((a0+a1)+(a2+a3));
            if (j == n) continue;
            if (d2 < dist[15]) {
                float dd = d2; int jj = j;
#pragma unroll
                for (int s = 0; s < 16; s++) {
                    if (dd < dist[s]) {
                        float td = dist[s]; int ti = ind[s];
                        dist[s] = dd; ind[s] = jj;
                        dd = td; jj = ti;
                    }
                }
            }
        }
    }
#pragma unroll
    for (int s = 0; s < 16; s++) {
        int o = ((b*4 + js)*16 + s)*Nn + n;
        d_pdist[o] = dist[s];
        d_pidx[o]  = ind[s];
    }
}

__global__ void knn_merge() {
    int e = blockIdx.x * 256 + threadIdx.x;     // 8192
    int b = e >> 12, n = e & 4095;

    float dist[16]; int ind[16];
#pragma unroll
    for (int s = 0; s < 16; s++) { dist[s] = __int_as_float(0x7f800000); ind[s] = 0; }

    for (int js = 0; js < 4; js++) {
#pragma unroll
        for (int s = 0; s < 16; s++) {
            int o = ((b*4 + js)*16 + s)*Nn + n;
            float dd = d_pdist[o];
            int jj = d_pidx[o];
            if (dd < dist[15]) {
#pragma unroll
                for (int t = 0; t < 16; t++) {
                    if (dd < dist[t]) {
                        float td = dist[t]; int ti = ind[t];
                        dist[t] = dd; ind[t] = jj;
                        dd = td; jj = ti;
                    }
                }
            }
        }
    }
#pragma unroll
    for (int s = 0; s < 16; s++)
        d_idx[(b*Kk + s)*Nn + n] = ind[s];
}

// ---------------- U kernel (fp32 FFMA, tiny) ----------------
__global__ __launch_bounds__(256) void u_kern(const float* __restrict__ x,
                                              const float* __restrict__ b1) {
    extern __shared__ float sm[];
    float* Ws = sm;
    float* xs = sm + 16384;
    int bx = blockIdx.x;
    int ng = bx & 127;
    int d  = (bx >> 7) % 3;
    int b  = bx / 384;
    int n0 = ng * 32;

    for (int e = threadIdx.x; e < 4096; e += 256)
        ((float4*)Ws)[e] = ((const float4*)d_AT)[e];
    for (int e = threadIdx.x; e < 2048; e += 256) {
        int c = e >> 5, p = e & 31;
        xs[c*36 + p] = x[((b*Cch + c)*Dd + d)*Nn + n0 + p];
    }
    __syncthreads();

    int o = threadIdx.x;
    float acc[32];
#pragma unroll
    for (int p = 0; p < 32; p++) acc[p] = 0.f;
#pragma unroll 4
    for (int c = 0; c < 64; c++) {
        float w = Ws[c*256 + o];
        const float4* xv = (const float4*)(xs + c*36);
#pragma unroll
        for (int p4 = 0; p4 < 8; p4++) {
            float4 v = xv[p4];
            acc[4*p4+0] = fmaf(w, v.x, acc[4*p4+0]);
            acc[4*p4+1] = fmaf(w, v.y, acc[4*p4+1]);
            acc[4*p4+2] = fmaf(w, v.z, acc[4*p4+2]);
            acc[4*p4+3] = fmaf(w, v.w, acc[4*p4+3]);
        }
    }
    float bb = b1[o];
    __half* dst = d_U + (((b*Dd + d)*Nn) + n0)*Hh + o;
#pragma unroll
    for (int p = 0; p < 32; p++) dst[p*Hh] = __float2half_rn(acc[p] + bb);
}

// ---------------- V via fp16 mma: V[128p][256o] = gathered_pts . BT^T ----------------
// SMEM: As [128][72] half = 18432B @0 ; Bs [256][72] half = 36864B @18432 ; total 55296
__global__ __launch_bounds__(256) void v_mma() {
    extern __shared__ __half smh[];
    __shared__ int sidx[128];
    __half* As = smh;                     // stride 72
    __half* Bs = smh + 9216;              // stride 72
    int tid = threadIdx.x;
    int wid = tid >> 5, lid = tid & 31;
    int row = lid >> 2, tg = lid & 3;

    int bx = blockIdx.x;                  // 1024 = 2b * 512
    int ng = bx & 511;
    int b  = bx >> 9;
    int n0 = ng * 8;

    if (tid < 128) {
        int nl = tid >> 4, kk = tid & 15;
        sidx[tid] = d_idx[(b*16 + kk)*4096 + n0 + nl];
    }
    // stage BT [o][c]
    for (int e = tid; e < 2048; e += 256) {
        int o = e >> 3, iv = e & 7;
        *(uint4*)(Bs + o*72 + iv*8) = *(const uint4*)(d_BTh + o*64 + iv*8);
    }
    __syncthreads();
    // gather A rows
    for (int e = tid; e < 2048; e += 256) {
        int p = e >> 4, hv = e & 15;
        *(uint2*)(As + p*72 + hv*4) = *(const uint2*)(d_ptsTh + (b*4096 + sidx[p])*64 + hv*4);
    }
    __syncthreads();

    int pb = (wid & 1) * 64;
    int ob = (wid >> 1) * 64;
    float acc[4][8][4];
#pragma unroll
    for (int mi = 0; mi < 4; mi++)
#pragma unroll
        for (int ni = 0; ni < 8; ni++)
#pragma unroll
            for (int r = 0; r < 4; r++) acc[mi][ni][r] = 0.f;

#pragma unroll
    for (int ks = 0; ks < 4; ks++) {
        int kb = ks*16;
        uint32_t a[4][4];
#pragma unroll
        for (int mi = 0; mi < 4; mi++) {
            int p0 = pb + mi*16 + row;
            a[mi][0] = ldh2(As + p0*72 + kb + 2*tg);
            a[mi][1] = ldh2(As + (p0+8)*72 + kb + 2*tg);
            a[mi][2] = ldh2(As + p0*72 + kb + 2*tg + 8);
            a[mi][3] = ldh2(As + (p0+8)*72 + kb + 2*tg + 8);
        }
        uint32_t bq[8][2];
#pragma unroll
        for (int ni = 0; ni < 8; ni++) {
            int o = ob + ni*8 + row;
            bq[ni][0] = ldh2(Bs + o*72 + kb + 2*tg);
            bq[ni][1] = ldh2(Bs + o*72 + kb + 2*tg + 8);
        }
#pragma unroll
        for (int mi = 0; mi < 4; mi++)
#pragma unroll
            for (int ni = 0; ni < 8; ni++)
                mma_fp16(acc[mi][ni], a[mi], bq[ni]);
    }

    // write V: row p -> (kk = p&15, n = n0 + (p>>4))
#pragma unroll
    for (int mi = 0; mi < 4; mi++) {
        int p0 = pb + mi*16 + row;
#pragma unroll
        for (int half_ = 0; half_ < 2; half_++) {
            int p = p0 + half_*8;
            int nl = p >> 4, kk = p & 15;
            __half* dst = d_V + ((b*16 + kk)*4096 + n0 + nl)*256;
#pragma unroll
            for (int ni = 0; ni < 8; ni++) {
                int o = ob + ni*8 + 2*tg;
                float c0 = acc[mi][ni][half_*2 + 0];
                float c1 = acc[mi][ni][half_*2 + 1];
                *(__half2*)(dst + o) = __floats2half2_rn(c0, c1);
            }
        }
    }
}

// ---------------- fp16 mma fused layer2+layer3+max+residual ----------------
// SMEM bytes:
//   h1/h2 : [128][264] half @0        (67584)
//   BUF   : 2 x [256][40] half @67584 (40960)   | W3s [64][264] half | r [128][66] f32
//   b2s f32 @108544 (1024) ; b3s f32 @109568 (256) ; TOT 109824
#define SMB_BUF 67584
#define SMB_B2  108544
#define SMB_B3  109568
#define SMB_TOT 109824

__global__ __launch_bounds__(256, 1) void mlp2_mma(const float* __restrict__ x,
                                                   const float* __restrict__ b2,
                                                   const float* __restrict__ b3,
                                                   float* __restrict__ out) {
    extern __shared__ char smem[];
    __half* smh = (__half*)smem;
    float* b2s = (float*)(smem + SMB_B2);
    float* b3s = (float*)(smem + SMB_B3);
    int tid = threadIdx.x;
    int wid = tid >> 5, lid = tid & 31;
    int row = lid >> 2, tg = lid & 3;

    int bx = blockIdx.x;                  // 3072 = 2*3*512
    int ng = bx & 511;
    int d  = (bx >> 9) % 3;
    int b  = bx / 1536;
    int n0 = ng * 8;

    if (tid < 256) b2s[tid] = b2[tid];
    if (tid < 64)  b3s[tid] = b3[tid];

    // ---- h1 = relu(U+V) in half, [p][264] ----
    {
        const uint4* Vp = (const uint4*)d_V;
        const uint4* Up = (const uint4*)d_U;
        for (int e = tid; e < 4096; e += 256) {
            int p = e >> 5, iv = e & 31;
            int nl = p >> 4, kk = p & 15;
            uint4 v = Vp[((b*16 + kk)*4096 + n0 + nl)*32 + iv];
            uint4 u = Up[((b*3  + d )*4096 + n0 + nl)*32 + iv];
            __half2 z = __float2half2_rn(0.f);
            uint4 h;
            *(__half2*)&h.x = __hmax2(__hadd2(*(__half2*)&u.x, *(__half2*)&v.x), z);
            *(__half2*)&h.y = __hmax2(__hadd2(*(__half2*)&u.y, *(__half2*)&v.y), z);
            *(__half2*)&h.z = __hmax2(__hadd2(*(__half2*)&u.z, *(__half2*)&v.z), z);
            *(__half2*)&h.w = __hmax2(__hadd2(*(__half2*)&u.w, *(__half2*)&v.w), z);
            *(uint4*)(smh + p*264 + iv*8) = h;
        }
    }

    // ---- GEMM1: D[128p][256o] = h1 . W2^T (K=256, chunks of 32) ----
    int wm = wid & 1, wn = wid >> 1;
    int pb = wm * 64, ob = wn * 64;

    float acc[4][8][4];
#pragma unroll
    for (int mi = 0; mi < 4; mi++)
#pragma unroll
        for (int ni = 0; ni < 8; ni++)
#pragma unroll
            for (int r = 0; r < 4; r++) acc[mi][ni][r] = 0.f;

    const uint4* W2v = (const uint4*)d_W2h;    // 8 halves per uint4, 32 per row
    uint4 g[4];
#pragma unroll
    for (int j = 0; j < 4; j++) g[j] = W2v[tid*32 + j];

    for (int ch = 0; ch < 8; ch++) {
        int buf = ch & 1;
        __half* Bsw = smh + SMB_BUF/2 + buf*10240;
#pragma unroll
        for (int j = 0; j < 4; j++)
            *(uint4*)(Bsw + tid*40 + j*8) = g[j];
        __syncthreads();
        if (ch < 7) {
#pragma unroll
            for (int j = 0; j < 4; j++) g[j] = W2v[tid*32 + (ch+1)*4 + j];
        }
        const __half* Bsr = smh + SMB_BUF/2 + buf*10240;
#pragma unroll
        for (int k16 = 0; k16 < 2; k16++) {
            int kb = ch*32 + k16*16;
            int kl = k16*16;
            uint32_t a[4][4];
#pragma unroll
            for (int mi = 0; mi < 4; mi++) {
                int p0 = pb + mi*16 + row;
                a[mi][0] = ldh2(smh + p0*264 + kb + 2*tg);
                a[mi][1] = ldh2(smh + (p0+8)*264 + kb + 2*tg);
                a[mi][2] = ldh2(smh + p0*264 + kb + 2*tg + 8);
                a[mi][3] = ldh2(smh + (p0+8)*264 + kb + 2*tg + 8);
            }
            uint32_t bq[8][2];
#pragma unroll
            for (int ni = 0; ni < 8; ni++) {
                int o = ob + ni*8 + row;
                bq[ni][0] = ldh2(Bsr + o*40 + kl + 2*tg);
                bq[ni][1] = ldh2(Bsr + o*40 + kl + 2*tg + 8);
            }
#pragma unroll
            for (int mi = 0; mi < 4; mi++)
#pragma unroll
                for (int ni = 0; ni < 8; ni++)
                    mma_fp16(acc[mi][ni], a[mi], bq[ni]);
        }
        __syncthreads();
    }

    // ---- epilogue1: h2 = relu(D + b2) -> half, back into h1 region ----
#pragma unroll
    for (int mi = 0; mi < 4; mi++) {
#pragma unroll
        for (int ni = 0; ni < 8; ni++) {
            int p = pb + mi*16 + row;
            int o = ob + ni*8 + 2*tg;
            float bo0 = b2s[o], bo1 = b2s[o+1];
            float v00 = fmaxf(acc[mi][ni][0] + bo0, 0.f);
            float v01 = fmaxf(acc[mi][ni][1] + bo1, 0.f);
            float v10 = fmaxf(acc[mi][ni][2] + bo0, 0.f);
            float v11 = fmaxf(acc[mi][ni][3] + bo1, 0.f);
            *(__half2*)(smh + p*264 + o)     = __floats2half2_rn(v00, v01);
            *(__half2*)(smh + (p+8)*264 + o) = __floats2half2_rn(v10, v11);
        }
    }
    __syncthreads();

    // ---- stage W3h [64c][264] into BUF region ----
    {
        __half* W3s = smh + SMB_BUF/2;
        for (int e = tid; e < 2048; e += 256) {
            int c = e >> 5, iv = e & 31;
            *(uint4*)(W3s + c*264 + iv*8) = *(const uint4*)(d_W3h + c*256 + iv*8);
        }
    }
    __syncthreads();

    // ---- GEMM2: D2[128p][64c] = h2 . W3^T (K=256) ----
    int pb2 = (wid & 1) * 64;
    int cb  = (wid >> 1) * 16;
    float ac2[4][2][4];
#pragma unroll
    for (int mi = 0; mi < 4; mi++)
#pragma unroll
        for (int ni = 0; ni < 2; ni++)
#pragma unroll
            for (int r = 0; r < 4; r++) ac2[mi][ni][r] = 0.f;

    const __half* W3s = smh + SMB_BUF/2;
#pragma unroll 4
    for (int ks = 0; ks < 16; ks++) {
        int kb = ks*16;
        uint32_t a[4][4];
#pragma unroll
        for (int mi = 0; mi < 4; mi++) {
            int p0 = pb2 + mi*16 + row;
            a[mi][0] = ldh2(smh + p0*264 + kb + 2*tg);
            a[mi][1] = ldh2(smh + (p0+8)*264 + kb + 2*tg);
            a[mi][2] = ldh2(smh + p0*264 + kb + 2*tg + 8);
            a[mi][3] = ldh2(smh + (p0+8)*264 + kb + 2*tg + 8);
        }
        uint32_t bq[2][2];
#pragma unroll
        for (int ni = 0; ni < 2; ni++) {
            int c = cb + ni*8 + row;
            bq[ni][0] = ldh2(W3s + c*264 + kb + 2*tg);
            bq[ni][1] = ldh2(W3s + c*264 + kb + 2*tg + 8);
        }
#pragma unroll
        for (int mi = 0; mi < 4; mi++)
#pragma unroll
            for (int ni = 0; ni < 2; ni++)
                mma_fp16(ac2[mi][ni], a[mi], bq[ni]);
    }
    __syncthreads();

    // ---- stage r = D2 -> BUF region as f32 [p][66] ----
    {
        float* rsm = (float*)(smem + SMB_BUF);
#pragma unroll
        for (int mi = 0; mi < 4; mi++) {
#pragma unroll
            for (int ni = 0; ni < 2; ni++) {
                int p = pb2 + mi*16 + row;
                int c = cb + ni*8 + 2*tg;
                *(float2*)(rsm + p*66 + c)     = make_float2(ac2[mi][ni][0], ac2[mi][ni][1]);
                *(float2*)(rsm + (p+8)*66 + c) = make_float2(ac2[mi][ni][2], ac2[mi][ni][3]);
            }
        }
    }
    __syncthreads();

    // ---- max over k + bias + residual ----
    {
        const float* rsm = (const float*)(smem + SMB_BUF);
        for (int e = tid; e < 512; e += 256) {
            int nl = e >> 6, c = e & 63;
            float m = -3.4e38f;
#pragma unroll
            for (int kk = 0; kk < 16; kk++)
                m = fmaxf(m, rsm[(nl*16 + kk)*66 + c]);
            int oi = ((b*64 + c)*3 + d)*4096 + n0 + nl;
            out[oi] = m + b3s[c] + x[oi];
        }
    }
}

// ---------------- launch ----------------
extern "C" void kernel_launch(void* const* d_in, const int* in_sizes, int n_in,
                              void* d_out, int out_size) {
    const float* x  = (const float*)d_in[0];
    const float* W1 = (const float*)d_in[1];
    const float* b1 = (const float*)d_in[2];
    const float* W2 = (const float*)d_in[3];
    const float* b2 = (const float*)d_in[4];
    const float* W3 = (const float*)d_in[5];
    const float* b3 = (const float*)d_in[6];
    float* out = (float*)d_out;

    static bool attr_done = false;
    if (!attr_done) {
        cudaFuncSetAttribute(u_kern,   cudaFuncAttributeMaxDynamicSharedMemorySize, 74752);
        cudaFuncSetAttribute(v_mma,    cudaFuncAttributeMaxDynamicSharedMemorySize, 55296);
        cudaFuncSetAttribute(mlp2_mma, cudaFuncAttributeMaxDynamicSharedMemorySize, SMB_TOT);
        attr_done = true;
    }

    prep_w<<<64, 256>>>(W1);
    prep_w23<<<320, 256>>>(W2, W3);
    mean_k<<<2048, 256>>>(x);
    transpose_k<<<2048, 256>>>();
    sq_k<<<32, 256>>>();
    knn_part<<<256, 128>>>();
    knn_merge<<<32, 256>>>();
    u_kern<<<768, 256, 74752>>>(x, b1);
    v_mma<<<1024, 256, 55296>>>();
    mlp2_mma<<<3072, 256, SMB_TOT>>>(x, b2, b3, out);
}